// round 14
// baseline (speedup 1.0000x reference)
#include <cuda_runtime.h>
#include <math.h>
#include <stdint.h>

#define NAT   50000
#define NP    1000000
#define MSGS  104
#define NSM   152
#define SCB   512
#define NBLK  ((NAT + SCB - 1) / SCB)   /* 98 */
typedef unsigned long long ull;

__device__ float g_Msum2[(size_t)NAT * 144];
__device__ float g_S[NAT];
__device__ float g_msg[(size_t)NAT * MSGS];
__device__ int   g_cnt[NAT];                  // zero at load; gatherw re-zeroes
__device__ int   g_loff[NAT];
__device__ int   g_lcur[NAT];
__device__ int   g_bsum[NBLK];
__device__ int   g_bbase[NBLK];
__device__ int   g_plist[NP];
__device__ int   g_scan_done;                 // zero at load; scan re-zeroes

__device__ __forceinline__ ull pack2(float x, float y) {
    ull r; asm("mov.b64 %0, {%1, %2};" : "=l"(r) : "f"(x), "f"(y)); return r;
}
__device__ __forceinline__ ull dup2(float x) {
    ull r; asm("mov.b64 %0, {%1, %1};" : "=l"(r) : "f"(x)); return r;
}
__device__ __forceinline__ void unpack2(ull v, float& x, float& y) {
    asm("mov.b64 {%0, %1}, %2;" : "=f"(x), "=f"(y) : "l"(v));
}
__device__ __forceinline__ ull fma2(ull a, ull b, ull c) {
    ull d; asm("fma.rn.f32x2 %0, %1, %2, %3;" : "=l"(d) : "l"(a), "l"(b), "l"(c));
    return d;
}
__device__ __forceinline__ float gelu_exact(float x) {
    return 0.5f * x * (1.0f + erff(x * 0.70710678118654752440f));
}

// ---- k_cnt: per-atom pair counts, 4 pairs/thread ----
__global__ void __launch_bounds__(256) k_cnt(const int4* __restrict__ idxj4) {
    int i = blockIdx.x * 256 + threadIdx.x;
    if (i >= NP / 4) return;
    int4 v = __ldg(idxj4 + i);
    if (v.x >= 0 && v.x < NAT) atomicAdd(&g_cnt[v.x], 1);
    if (v.y >= 0 && v.y < NAT) atomicAdd(&g_cnt[v.y], 1);
    if (v.z >= 0 && v.z < NAT) atomicAdd(&g_cnt[v.z], 1);
    if (v.w >= 0 && v.w < NAT) atomicAdd(&g_cnt[v.w], 1);
}

// ---- k_scan: block-local prefix + last-block global prefix (fused) ----
__global__ void __launch_bounds__(SCB) k_scan() {
    __shared__ int s[SCB];
    __shared__ int amLast;
    int b = blockIdx.x, t = threadIdx.x;
    int a = b * SCB + t;
    int c = (a < NAT) ? g_cnt[a] : 0;
    s[t] = c;
    __syncthreads();
    for (int off = 1; off < SCB; off <<= 1) {
        int v = (t >= off) ? s[t - off] : 0;
        __syncthreads();
        s[t] += v;
        __syncthreads();
    }
    int excl = s[t] - c;
    if (a < NAT) { g_loff[a] = excl; g_lcur[a] = excl; }
    if (t == SCB - 1) g_bsum[b] = s[SCB - 1];
    __threadfence();
    if (t == 0) amLast = (atomicAdd(&g_scan_done, 1) == NBLK - 1);
    __syncthreads();
    if (amLast) {
        int v = (t < NBLK) ? g_bsum[t] : 0;
        s[t] = v;
        __syncthreads();
        for (int off = 1; off < 128; off <<= 1) {
            int u = (t >= off && t < 128) ? s[t - off] : 0;
            __syncthreads();
            if (t < 128) s[t] += u;
            __syncthreads();
        }
        if (t < NBLK) g_bbase[t] = s[t] - v;
        if (t == 0) g_scan_done = 0;          // reset for graph replay
    }
}

// ---- k_place ----
__global__ void __launch_bounds__(256) k_place(const int* __restrict__ idxj) {
    int p = blockIdx.x * 256 + threadIdx.x;
    if (p >= NP) return;
    int a = __ldg(idxj + p);
    if (a < 0 || a >= NAT) return;
    int pos = g_bbase[a >> 9] + atomicAdd(&g_lcur[a], 1);
    g_plist[pos] = p;
}

// ---- k_gatherw v2 (R13-exact): warp-per-atom circulant Gram + S, pipelined ----
__global__ void __launch_bounds__(512) k_gatherw(const float* __restrict__ gv,
                                                 const float* __restrict__ gs) {
    int w = threadIdx.x >> 5, lane = threadIdx.x & 31;
    int a = blockIdx.x * 16 + w;
    if (a >= NAT) return;
    int g = lane & 15, half = lane >> 4;

    int beg = g_bbase[a >> 9] + g_loff[a];
    int cnt = g_cnt[a];

    float acc[9];
#pragma unroll
    for (int o = 0; o < 9; o++) acc[o] = 0.f;
    float acc_s = 0.f;

    float cx = 0.f, cy = 0.f, cz = 0.f, cs = 0.f;
    if (half < cnt) {
        int p = g_plist[beg + half];
        const float* vp = gv + (size_t)p * 48;
        cx = __ldg(vp + g);
        cy = __ldg(vp + 16 + g);
        cz = __ldg(vp + 32 + g);
        cs = __ldg(gs + (size_t)p * 16 + g);
    }

    int rounds = (cnt + 1) >> 1;
    for (int r = 0; r < rounds; r++) {
        float nx = 0.f, ny = 0.f, nz = 0.f, ns = 0.f;
        int nrec = 2 * (r + 1) + half;
        if (nrec < cnt) {
            int p = g_plist[beg + nrec];
            const float* vp = gv + (size_t)p * 48;
            nx = __ldg(vp + g);
            ny = __ldg(vp + 16 + g);
            nz = __ldg(vp + 32 + g);
            ns = __ldg(gs + (size_t)p * 16 + g);
        }
#pragma unroll
        for (int o = 0; o < 9; o++) {
            int src = (g + o) & 15;
            float px = __shfl_sync(0xffffffffu, cx, src, 16);
            float py = __shfl_sync(0xffffffffu, cy, src, 16);
            float pz = __shfl_sync(0xffffffffu, cz, src, 16);
            acc[o] += cx * px + cy * py + cz * pz;
        }
        acc_s += cs;
        cx = nx; cy = ny; cz = nz; cs = ns;
    }

#pragma unroll
    for (int o = 0; o < 9; o++)
        acc[o] += __shfl_xor_sync(0xffffffffu, acc[o], 16);
#pragma unroll
    for (int off = 16; off >= 1; off >>= 1)
        acc_s += __shfl_xor_sync(0xffffffffu, acc_s, off);

    if (half == 0) {
        float* dst = g_Msum2 + (size_t)a * 144;
#pragma unroll
        for (int o = 0; o < 9; o++) dst[o * 16 + g] = acc[o];
    }
    if (lane == 0) {
        g_S[a] = acc_s;
        g_cnt[a] = 0;
    }
}

// ---- k_atom (R13-exact) ----
__global__ void __launch_bounds__(512) k_atom(const float* __restrict__ emb,
                                              const float* __restrict__ pc,
                                              const float* __restrict__ agh) {
    extern __shared__ float aghs[];
    int tid = threadIdx.x;
    for (int i = tid; i < 32768; i += 512) {
        int f = i >> 9, rem = i & 511, g = rem >> 5, h = rem & 31;
        aghs[f * 512 + (g >> 1) * 64 + h * 2 + (g & 1)] = __ldg(agh + i);
    }
    __syncthreads();

    int lane = tid & 31, wid = tid >> 5;
    int gw = blockIdx.x * 16 + wid, GW = gridDim.x * 16;

    for (int base = gw * 4; base < NAT; base += GW * 4) {
        float e0[4], e1[4];
#pragma unroll
        for (int i = 0; i < 4; i++) {
            int ai = (base + i < NAT) ? base + i : NAT - 1;
            e0[i] = __ldg(emb + (size_t)ai * 64 + lane);
            e1[i] = __ldg(emb + (size_t)ai * 64 + 32 + lane);
        }
        ull T2[4][8];
#pragma unroll
        for (int i = 0; i < 4; i++)
#pragma unroll
            for (int g2 = 0; g2 < 8; g2++) T2[i][g2] = 0ull;

#pragma unroll 4
        for (int fl = 0; fl < 32; fl++) {
            ull x0 = dup2(__shfl_sync(0xffffffffu, e0[0], fl));
            ull x1 = dup2(__shfl_sync(0xffffffffu, e0[1], fl));
            ull x2 = dup2(__shfl_sync(0xffffffffu, e0[2], fl));
            ull x3 = dup2(__shfl_sync(0xffffffffu, e0[3], fl));
            const ull* ap = reinterpret_cast<const ull*>(aghs + fl * 512) + lane;
#pragma unroll
            for (int g2 = 0; g2 < 8; g2++) {
                ull av = ap[g2 * 32];
                T2[0][g2] = fma2(x0, av, T2[0][g2]);
                T2[1][g2] = fma2(x1, av, T2[1][g2]);
                T2[2][g2] = fma2(x2, av, T2[2][g2]);
                T2[3][g2] = fma2(x3, av, T2[3][g2]);
            }
        }
#pragma unroll 4
        for (int fl = 0; fl < 32; fl++) {
            ull x0 = dup2(__shfl_sync(0xffffffffu, e1[0], fl));
            ull x1 = dup2(__shfl_sync(0xffffffffu, e1[1], fl));
            ull x2 = dup2(__shfl_sync(0xffffffffu, e1[2], fl));
            ull x3 = dup2(__shfl_sync(0xffffffffu, e1[3], fl));
            const ull* ap = reinterpret_cast<const ull*>(aghs + (32 + fl) * 512) + lane;
#pragma unroll
            for (int g2 = 0; g2 < 8; g2++) {
                ull av = ap[g2 * 32];
                T2[0][g2] = fma2(x0, av, T2[0][g2]);
                T2[1][g2] = fma2(x1, av, T2[1][g2]);
                T2[2][g2] = fma2(x2, av, T2[2][g2]);
                T2[3][g2] = fma2(x3, av, T2[3][g2]);
            }
        }

#pragma unroll
        for (int i = 0; i < 4; i++) {
            int a = base + i;
            if (a >= NAT) break;
            float T[16];
#pragma unroll
            for (int g2 = 0; g2 < 8; g2++) unpack2(T2[i][g2], T[2*g2], T[2*g2+1]);

            const float* mr = g_Msum2 + (size_t)a * 144;
            float mv0 = mr[lane], mv1 = mr[32+lane], mv2 = mr[64+lane], mv3 = mr[96+lane];
            float mv4 = (lane < 16) ? mr[128 + lane] : 0.f;
            float Sv = g_S[a];
            float qv = __ldg(pc + a);

            float qd = 0.f, qo = 0.f, q8 = 0.f;
#pragma unroll
            for (int o = 0; o < 9; o++)
#pragma unroll
                for (int g = 0; g < 16; g++) {
                    const int idx = o * 16 + g;
                    float msrc = (idx < 32) ? mv0 : (idx < 64) ? mv1 : (idx < 96) ? mv2
                               : (idx < 128) ? mv3 : mv4;
                    float mm = __shfl_sync(0xffffffffu, msrc, idx & 31);
                    float t = T[g] * T[(g + o) & 15];
                    if (o == 0)      qd = fmaf(mm, t, qd);
                    else if (o == 8) q8 = fmaf(mm, t, q8);
                    else             qo = fmaf(mm, t, qo);
                }
            float Q = (qd + q8) + 2.f * qo;

            float* mg = g_msg + (size_t)a * MSGS;
            mg[lane]      = e0[i] * Sv;
            mg[32 + lane] = e1[i] * Sv;
            mg[64 + lane] = Q;
            if (lane < 8) mg[96 + lane] = (lane == 0) ? qv * Sv : 0.f;
        }
    }
}

// ---- k_mlp (R9-exact) ----
#define oWT1 0
#define oWT2 12544
#define oWT3 28928
#define oB1  37632
#define oB2  37760
#define oB3  37888
#define oHS  37960
#define oMS  46152
#define SMEM_MLP (52808 * 4)

__global__ void __launch_bounds__(512) k_mlp(const float* __restrict__ W1,
                                             const float* __restrict__ b1,
                                             const float* __restrict__ W2,
                                             const float* __restrict__ b2,
                                             const float* __restrict__ W3,
                                             const float* __restrict__ b3,
                                             float* __restrict__ out) {
    extern __shared__ float sm[];
    int tid = threadIdx.x;
    for (int idx = tid; idx < 6272; idx += 512) {
        int k2 = idx >> 7, c = idx & 127;
        sm[oWT1 + idx*2]   = (2*k2   < 97) ? W1[(2*k2)  *128 + c] : 0.f;
        sm[oWT1 + idx*2+1] = (2*k2+1 < 97) ? W1[(2*k2+1)*128 + c] : 0.f;
    }
    for (int idx = tid; idx < 8192; idx += 512) {
        int k2 = idx >> 7, c = idx & 127;
        sm[oWT2 + idx*2]   = W2[(2*k2)  *128 + c];
        sm[oWT2 + idx*2+1] = W2[(2*k2+1)*128 + c];
    }
    for (int idx = tid; idx < 4352; idx += 512) {
        int k2 = idx / 68, c = idx - k2 * 68;
        sm[oWT3 + idx*2]   = (c < 66) ? W3[(2*k2)  *66 + c] : 0.f;
        sm[oWT3 + idx*2+1] = (c < 66) ? W3[(2*k2+1)*66 + c] : 0.f;
    }
    if (tid < 128) { sm[oB1 + tid] = b1[tid]; sm[oB2 + tid] = b2[tid]; }
    if (tid < 72)  sm[oB3 + tid] = (tid < 66) ? b3[tid] : 0.f;
    __syncthreads();

    int lane = tid & 31, w = tid >> 5;
    float* ms = sm + oMS + w * 416;
    float* hs = sm + oHS + w * 512;
    const ull* wt1u = reinterpret_cast<const ull*>(sm + oWT1);
    const ull* wt2u = reinterpret_cast<const ull*>(sm + oWT2);
    const ull* wt3u = reinterpret_cast<const ull*>(sm + oWT3);
    float b1c[4] = { sm[oB1+lane], sm[oB1+32+lane], sm[oB1+64+lane], sm[oB1+96+lane] };
    float b2c[4] = { sm[oB2+lane], sm[oB2+32+lane], sm[oB2+64+lane], sm[oB2+96+lane] };
    float bc0 = sm[oB3 + lane], bc1 = sm[oB3 + 32 + lane];
    float bc2 = sm[oB3 + 64 + (lane & 1)];
    int c2i = 64 + (lane & 1);

    float* da = out;
    float* dq = out + (size_t)NAT * 64;
    float* fo = out + (size_t)NAT * 65;

    int gw = blockIdx.x * 16 + w, GW = gridDim.x * 16;
    for (int base = gw * 4; base < NAT; base += GW * 4) {
#pragma unroll
        for (int i = 0; i < 4; i++) {
            int ai = (base + i < NAT) ? base + i : NAT - 1;
            const float4* mrow = reinterpret_cast<const float4*>(g_msg + (size_t)ai * MSGS);
            if (lane < 26) reinterpret_cast<float4*>(ms + i * 104)[lane] = __ldg(mrow + lane);
        }
        __syncwarp();

        ull a1[4][4];
#pragma unroll
        for (int i = 0; i < 4; i++)
#pragma unroll
            for (int c = 0; c < 4; c++) a1[i][c] = pack2(b1c[c], 0.f);
        for (int k2 = 0; k2 < 49; k2++) {
            const ull* wr = wt1u + k2 * 128;
            ull w0 = wr[lane], w1 = wr[32+lane], w2 = wr[64+lane], w3 = wr[96+lane];
#pragma unroll
            for (int i = 0; i < 4; i++) {
                ull x2 = *reinterpret_cast<const ull*>(ms + i * 104 + 2 * k2);
                a1[i][0] = fma2(w0, x2, a1[i][0]);
                a1[i][1] = fma2(w1, x2, a1[i][1]);
                a1[i][2] = fma2(w2, x2, a1[i][2]);
                a1[i][3] = fma2(w3, x2, a1[i][3]);
            }
        }
        __syncwarp();
#pragma unroll
        for (int i = 0; i < 4; i++)
#pragma unroll
            for (int c = 0; c < 4; c++) {
                float lo, hi; unpack2(a1[i][c], lo, hi);
                hs[i * 128 + c * 32 + lane] = gelu_exact(lo + hi);
            }
        __syncwarp();

        ull a2[4][4];
#pragma unroll
        for (int i = 0; i < 4; i++)
#pragma unroll
            for (int c = 0; c < 4; c++) a2[i][c] = pack2(b2c[c], 0.f);
        for (int k2 = 0; k2 < 64; k2++) {
            const ull* wr = wt2u + k2 * 128;
            ull w0 = wr[lane], w1 = wr[32+lane], w2 = wr[64+lane], w3 = wr[96+lane];
#pragma unroll
            for (int i = 0; i < 4; i++) {
                ull x2 = *reinterpret_cast<const ull*>(hs + i * 128 + 2 * k2);
                a2[i][0] = fma2(w0, x2, a2[i][0]);
                a2[i][1] = fma2(w1, x2, a2[i][1]);
                a2[i][2] = fma2(w2, x2, a2[i][2]);
                a2[i][3] = fma2(w3, x2, a2[i][3]);
            }
        }
        __syncwarp();
        float h2v[4][4];
#pragma unroll
        for (int i = 0; i < 4; i++)
#pragma unroll
            for (int c = 0; c < 4; c++) {
                float lo, hi; unpack2(a2[i][c], lo, hi);
                h2v[i][c] = gelu_exact(lo + hi);
            }
#pragma unroll
        for (int i = 0; i < 4; i++)
#pragma unroll
            for (int c = 0; c < 4; c++) hs[i * 128 + c * 32 + lane] = h2v[i][c];
        __syncwarp();

        ull c0[4], c1[4], cc2[4];
#pragma unroll
        for (int i = 0; i < 4; i++) {
            c0[i] = pack2(bc0, 0.f); c1[i] = pack2(bc1, 0.f); cc2[i] = pack2(bc2, 0.f);
        }
        for (int k2 = 0; k2 < 64; k2++) {
            const ull* wr = wt3u + k2 * 68;
            ull w0 = wr[lane], w1 = wr[32 + lane], w2 = wr[c2i];
#pragma unroll
            for (int i = 0; i < 4; i++) {
                ull x2 = *reinterpret_cast<const ull*>(hs + i * 128 + 2 * k2);
                c0[i]  = fma2(w0, x2, c0[i]);
                c1[i]  = fma2(w1, x2, c1[i]);
                cc2[i] = fma2(w2, x2, cc2[i]);
            }
        }

#pragma unroll
        for (int i = 0; i < 4; i++) {
            int a = base + i;
            if (a >= NAT) break;
            float l0, h0, l1, h1, l2, h2;
            unpack2(c0[i], l0, h0); unpack2(c1[i], l1, h1); unpack2(cc2[i], l2, h2);
            float r0 = l0 + h0, r1 = l1 + h1, r2 = l2 + h2;
            if (lane == 0)      dq[a] = r0;
            else if (lane == 1) fo[a] = r0;
            else                da[(size_t)a * 64 + (lane - 2)] = r0;
            da[(size_t)a * 64 + (30 + lane)] = r1;
            if (lane < 2) da[(size_t)a * 64 + (62 + lane)] = r2;
        }
    }
}

extern "C" void kernel_launch(void* const* d_in, const int* in_sizes, int n_in,
                              void* d_out, int out_size) {
    const float *emb = 0, *pc = 0, *gs = 0, *gv = 0, *agh = 0;
    const float *W1 = 0, *b1 = 0, *W2 = 0, *b2 = 0, *W3 = 0, *b3 = 0;
    const int* pidx = 0;
    for (int i = 0; i < n_in; i++) {
        switch (in_sizes[i]) {
            case 3200000:  emb = (const float*)d_in[i]; break;
            case 50000:    pc  = (const float*)d_in[i]; break;
            case 16000000: gs  = (const float*)d_in[i]; break;
            case 48000000: gv  = (const float*)d_in[i]; break;
            case 32768:    agh = (const float*)d_in[i]; break;
            case 16512:    W1  = (const float*)d_in[i]; break;
            case 16384:    W2  = (const float*)d_in[i]; break;
            case 8448:     W3  = (const float*)d_in[i]; break;
            case 128:      if (!b1) b1 = (const float*)d_in[i];
                           else     b2 = (const float*)d_in[i]; break;
            case 66:       b3  = (const float*)d_in[i]; break;
            case 2000000:  pidx = (const int*)d_in[i]; break;
            default: break;
        }
    }
    float* out = (float*)d_out;
    (void)out_size;

    cudaFuncSetAttribute(k_atom, cudaFuncAttributeMaxDynamicSharedMemorySize, 131072);
    cudaFuncSetAttribute(k_mlp,  cudaFuncAttributeMaxDynamicSharedMemorySize, SMEM_MLP);

    const int* idxj = pidx + NP;   // pair_indices[1]

    k_cnt<<<(NP / 4 + 255) / 256, 256>>>((const int4*)idxj);   // idx0
    k_scan<<<NBLK, SCB>>>();                                   // idx1
    k_place<<<(NP + 255) / 256, 256>>>(idxj);                  // idx2
    k_gatherw<<<(NAT + 15) / 16, 512>>>(gv, gs);               // idx3 <- profiled
    k_atom<<<NSM, 512, 131072>>>(emb, pc, agh);
    k_mlp<<<NSM, 512, SMEM_MLP>>>(W1, b1, W2, b2, W3, b3, out);
}

// round 15
// speedup vs baseline: 1.0339x; 1.0339x over previous
#include <cuda_runtime.h>
#include <math.h>
#include <stdint.h>

#define NAT   50000
#define NP    1000000
#define MSGS  104
#define NSM   152
#define SCB   512
#define NBLK  ((NAT + SCB - 1) / SCB)   /* 98 */
typedef unsigned long long ull;

__device__ float g_Msum2[(size_t)NAT * 144];
__device__ float g_S[NAT];                    // zero at load; k_atom re-zeroes
__device__ float g_msg[(size_t)NAT * MSGS];
__device__ int   g_cnt[NAT];                  // zero at load; gatherw re-zeroes
__device__ int   g_loff[NAT];
__device__ int   g_lcur[NAT];
__device__ int   g_bsum[NBLK];
__device__ int   g_bbase[NBLK];
__device__ int   g_plist[NP];
__device__ int   g_scan_done;                 // zero at load; scan re-zeroes

__device__ __forceinline__ ull pack2(float x, float y) {
    ull r; asm("mov.b64 %0, {%1, %2};" : "=l"(r) : "f"(x), "f"(y)); return r;
}
__device__ __forceinline__ ull dup2(float x) {
    ull r; asm("mov.b64 %0, {%1, %1};" : "=l"(r) : "f"(x)); return r;
}
__device__ __forceinline__ void unpack2(ull v, float& x, float& y) {
    asm("mov.b64 {%0, %1}, %2;" : "=f"(x), "=f"(y) : "l"(v));
}
__device__ __forceinline__ ull fma2(ull a, ull b, ull c) {
    ull d; asm("fma.rn.f32x2 %0, %1, %2, %3;" : "=l"(d) : "l"(a), "l"(b), "l"(c));
    return d;
}
__device__ __forceinline__ float gelu_exact(float x) {
    return 0.5f * x * (1.0f + erff(x * 0.70710678118654752440f));
}

// ---- k_hist: per-atom pair count + S (gs read once, coalesced) ----
__global__ void __launch_bounds__(256) k_hist(const float* __restrict__ gs,
                                              const int* __restrict__ idxj) {
    int p = blockIdx.x * 256 + threadIdx.x;
    if (p >= NP) return;
    const float4* gs4 = reinterpret_cast<const float4*>(gs) + (size_t)p * 4;
    float s = 0.f;
#pragma unroll
    for (int k = 0; k < 4; k++) {
        float4 t = __ldg(gs4 + k);
        s += (t.x + t.y) + (t.z + t.w);
    }
    int a = __ldg(idxj + p);
    if (a < 0 || a >= NAT) return;
    atomicAdd(&g_cnt[a], 1);
    atomicAdd(&g_S[a], s);
}

// ---- k_scan: fused block-local + last-block global prefix ----
__global__ void __launch_bounds__(SCB) k_scan() {
    __shared__ int s[SCB];
    __shared__ int amLast;
    int b = blockIdx.x, t = threadIdx.x;
    int a = b * SCB + t;
    int c = (a < NAT) ? g_cnt[a] : 0;
    s[t] = c;
    __syncthreads();
    for (int off = 1; off < SCB; off <<= 1) {
        int v = (t >= off) ? s[t - off] : 0;
        __syncthreads();
        s[t] += v;
        __syncthreads();
    }
    int excl = s[t] - c;
    if (a < NAT) { g_loff[a] = excl; g_lcur[a] = excl; }
    if (t == SCB - 1) g_bsum[b] = s[SCB - 1];
    __threadfence();
    if (t == 0) amLast = (atomicAdd(&g_scan_done, 1) == NBLK - 1);
    __syncthreads();
    if (amLast) {
        int v = (t < NBLK) ? g_bsum[t] : 0;
        s[t] = v;
        __syncthreads();
        for (int off = 1; off < 128; off <<= 1) {
            int u = (t >= off && t < 128) ? s[t - off] : 0;
            __syncthreads();
            if (t < 128) s[t] += u;
            __syncthreads();
        }
        if (t < NBLK) g_bbase[t] = s[t] - v;
        if (t == 0) g_scan_done = 0;
    }
}

// ---- k_place ----
__global__ void __launch_bounds__(256) k_place(const int* __restrict__ idxj) {
    int p = blockIdx.x * 256 + threadIdx.x;
    if (p >= NP) return;
    int a = __ldg(idxj + p);
    if (a < 0 || a >= NAT) return;
    int pos = g_bbase[a >> 9] + atomicAdd(&g_lcur[a], 1);
    g_plist[pos] = p;
}

// ---- k_gatherw v3: warp-per-atom circulant Gram; 2-ahead plist, 1-ahead gv ----
__global__ void __launch_bounds__(256) k_gatherw(const float* __restrict__ gv) {
    int w = threadIdx.x >> 5, lane = threadIdx.x & 31;
    int a = blockIdx.x * 8 + w;
    if (a >= NAT) return;
    int g = lane & 15, half = lane >> 4;

    int beg = g_bbase[a >> 9] + g_loff[a];
    int cnt = g_cnt[a];

    float acc[9];
#pragma unroll
    for (int o = 0; o < 9; o++) acc[o] = 0.f;

    // prefetch indices for rounds 0,1; data for round 0
    int p0 = (half < cnt) ? g_plist[beg + half] : -1;
    int p1 = (2 + half < cnt) ? g_plist[beg + 2 + half] : -1;
    float cx = 0.f, cy = 0.f, cz = 0.f;
    if (p0 >= 0) {
        const float* vp = gv + (size_t)p0 * 48;
        cx = __ldg(vp + g); cy = __ldg(vp + 16 + g); cz = __ldg(vp + 32 + g);
    }

    int rounds = (cnt + 1) >> 1;
    for (int r = 0; r < rounds; r++) {
        // index for round r+2, data for round r+1
        int i2 = 2 * (r + 2) + half;
        int p2 = (i2 < cnt) ? g_plist[beg + i2] : -1;
        float nx = 0.f, ny = 0.f, nz = 0.f;
        if (p1 >= 0) {
            const float* vp = gv + (size_t)p1 * 48;
            nx = __ldg(vp + g); ny = __ldg(vp + 16 + g); nz = __ldg(vp + 32 + g);
        }
#pragma unroll
        for (int o = 0; o < 9; o++) {
            int src = (g + o) & 15;
            float px = __shfl_sync(0xffffffffu, cx, src, 16);
            float py = __shfl_sync(0xffffffffu, cy, src, 16);
            float pz = __shfl_sync(0xffffffffu, cz, src, 16);
            acc[o] += cx * px + cy * py + cz * pz;
        }
        cx = nx; cy = ny; cz = nz;
        p1 = p2;
    }

#pragma unroll
    for (int o = 0; o < 9; o++)
        acc[o] += __shfl_xor_sync(0xffffffffu, acc[o], 16);

    if (half == 0) {
        float* dst = g_Msum2 + (size_t)a * 144;
#pragma unroll
        for (int o = 0; o < 9; o++) dst[o * 16 + g] = acc[o];
    }
    if (lane == 0) g_cnt[a] = 0;
}

// ---- k_atom: T = emb @ agh (f32x2), circulant quad form -> msg; re-zeroes S ----
__global__ void __launch_bounds__(512) k_atom(const float* __restrict__ emb,
                                              const float* __restrict__ pc,
                                              const float* __restrict__ agh) {
    extern __shared__ float aghs[];
    int tid = threadIdx.x;
    for (int i = tid; i < 32768; i += 512) {
        int f = i >> 9, rem = i & 511, g = rem >> 5, h = rem & 31;
        aghs[f * 512 + (g >> 1) * 64 + h * 2 + (g & 1)] = __ldg(agh + i);
    }
    __syncthreads();

    int lane = tid & 31, wid = tid >> 5;
    int gw = blockIdx.x * 16 + wid, GW = gridDim.x * 16;

    for (int base = gw * 4; base < NAT; base += GW * 4) {
        float e0[4], e1[4];
#pragma unroll
        for (int i = 0; i < 4; i++) {
            int ai = (base + i < NAT) ? base + i : NAT - 1;
            e0[i] = __ldg(emb + (size_t)ai * 64 + lane);
            e1[i] = __ldg(emb + (size_t)ai * 64 + 32 + lane);
        }
        ull T2[4][8];
#pragma unroll
        for (int i = 0; i < 4; i++)
#pragma unroll
            for (int g2 = 0; g2 < 8; g2++) T2[i][g2] = 0ull;

#pragma unroll 4
        for (int fl = 0; fl < 32; fl++) {
            ull x0 = dup2(__shfl_sync(0xffffffffu, e0[0], fl));
            ull x1 = dup2(__shfl_sync(0xffffffffu, e0[1], fl));
            ull x2 = dup2(__shfl_sync(0xffffffffu, e0[2], fl));
            ull x3 = dup2(__shfl_sync(0xffffffffu, e0[3], fl));
            const ull* ap = reinterpret_cast<const ull*>(aghs + fl * 512) + lane;
#pragma unroll
            for (int g2 = 0; g2 < 8; g2++) {
                ull av = ap[g2 * 32];
                T2[0][g2] = fma2(x0, av, T2[0][g2]);
                T2[1][g2] = fma2(x1, av, T2[1][g2]);
                T2[2][g2] = fma2(x2, av, T2[2][g2]);
                T2[3][g2] = fma2(x3, av, T2[3][g2]);
            }
        }
#pragma unroll 4
        for (int fl = 0; fl < 32; fl++) {
            ull x0 = dup2(__shfl_sync(0xffffffffu, e1[0], fl));
            ull x1 = dup2(__shfl_sync(0xffffffffu, e1[1], fl));
            ull x2 = dup2(__shfl_sync(0xffffffffu, e1[2], fl));
            ull x3 = dup2(__shfl_sync(0xffffffffu, e1[3], fl));
            const ull* ap = reinterpret_cast<const ull*>(aghs + (32 + fl) * 512) + lane;
#pragma unroll
            for (int g2 = 0; g2 < 8; g2++) {
                ull av = ap[g2 * 32];
                T2[0][g2] = fma2(x0, av, T2[0][g2]);
                T2[1][g2] = fma2(x1, av, T2[1][g2]);
                T2[2][g2] = fma2(x2, av, T2[2][g2]);
                T2[3][g2] = fma2(x3, av, T2[3][g2]);
            }
        }

#pragma unroll
        for (int i = 0; i < 4; i++) {
            int a = base + i;
            if (a >= NAT) break;
            float T[16];
#pragma unroll
            for (int g2 = 0; g2 < 8; g2++) unpack2(T2[i][g2], T[2*g2], T[2*g2+1]);

            const float* mr = g_Msum2 + (size_t)a * 144;
            float mv0 = mr[lane], mv1 = mr[32+lane], mv2 = mr[64+lane], mv3 = mr[96+lane];
            float mv4 = (lane < 16) ? mr[128 + lane] : 0.f;
            float Sv = g_S[a];
            float qv = __ldg(pc + a);

            float qd = 0.f, qo = 0.f, q8 = 0.f;
#pragma unroll
            for (int o = 0; o < 9; o++)
#pragma unroll
                for (int g = 0; g < 16; g++) {
                    const int idx = o * 16 + g;
                    float msrc = (idx < 32) ? mv0 : (idx < 64) ? mv1 : (idx < 96) ? mv2
                               : (idx < 128) ? mv3 : mv4;
                    float mm = __shfl_sync(0xffffffffu, msrc, idx & 31);
                    float t = T[g] * T[(g + o) & 15];
                    if (o == 0)      qd = fmaf(mm, t, qd);
                    else if (o == 8) q8 = fmaf(mm, t, q8);
                    else             qo = fmaf(mm, t, qo);
                }
            float Q = (qd + q8) + 2.f * qo;

            float* mg = g_msg + (size_t)a * MSGS;
            mg[lane]      = e0[i] * Sv;
            mg[32 + lane] = e1[i] * Sv;
            mg[64 + lane] = Q;
            if (lane < 8) mg[96 + lane] = (lane == 0) ? qv * Sv : 0.f;
            if (lane == 0) g_S[a] = 0.f;      // restore invariant for replay
        }
    }
}

// ---- k_mlp (R9-exact) ----
#define oWT1 0
#define oWT2 12544
#define oWT3 28928
#define oB1  37632
#define oB2  37760
#define oB3  37888
#define oHS  37960
#define oMS  46152
#define SMEM_MLP (52808 * 4)

__global__ void __launch_bounds__(512) k_mlp(const float* __restrict__ W1,
                                             const float* __restrict__ b1,
                                             const float* __restrict__ W2,
                                             const float* __restrict__ b2,
                                             const float* __restrict__ W3,
                                             const float* __restrict__ b3,
                                             float* __restrict__ out) {
    extern __shared__ float sm[];
    int tid = threadIdx.x;
    for (int idx = tid; idx < 6272; idx += 512) {
        int k2 = idx >> 7, c = idx & 127;
        sm[oWT1 + idx*2]   = (2*k2   < 97) ? W1[(2*k2)  *128 + c] : 0.f;
        sm[oWT1 + idx*2+1] = (2*k2+1 < 97) ? W1[(2*k2+1)*128 + c] : 0.f;
    }
    for (int idx = tid; idx < 8192; idx += 512) {
        int k2 = idx >> 7, c = idx & 127;
        sm[oWT2 + idx*2]   = W2[(2*k2)  *128 + c];
        sm[oWT2 + idx*2+1] = W2[(2*k2+1)*128 + c];
    }
    for (int idx = tid; idx < 4352; idx += 512) {
        int k2 = idx / 68, c = idx - k2 * 68;
        sm[oWT3 + idx*2]   = (c < 66) ? W3[(2*k2)  *66 + c] : 0.f;
        sm[oWT3 + idx*2+1] = (c < 66) ? W3[(2*k2+1)*66 + c] : 0.f;
    }
    if (tid < 128) { sm[oB1 + tid] = b1[tid]; sm[oB2 + tid] = b2[tid]; }
    if (tid < 72)  sm[oB3 + tid] = (tid < 66) ? b3[tid] : 0.f;
    __syncthreads();

    int lane = tid & 31, w = tid >> 5;
    float* ms = sm + oMS + w * 416;
    float* hs = sm + oHS + w * 512;
    const ull* wt1u = reinterpret_cast<const ull*>(sm + oWT1);
    const ull* wt2u = reinterpret_cast<const ull*>(sm + oWT2);
    const ull* wt3u = reinterpret_cast<const ull*>(sm + oWT3);
    float b1c[4] = { sm[oB1+lane], sm[oB1+32+lane], sm[oB1+64+lane], sm[oB1+96+lane] };
    float b2c[4] = { sm[oB2+lane], sm[oB2+32+lane], sm[oB2+64+lane], sm[oB2+96+lane] };
    float bc0 = sm[oB3 + lane], bc1 = sm[oB3 + 32 + lane];
    float bc2 = sm[oB3 + 64 + (lane & 1)];
    int c2i = 64 + (lane & 1);

    float* da = out;
    float* dq = out + (size_t)NAT * 64;
    float* fo = out + (size_t)NAT * 65;

    int gw = blockIdx.x * 16 + w, GW = gridDim.x * 16;
    for (int base = gw * 4; base < NAT; base += GW * 4) {
#pragma unroll
        for (int i = 0; i < 4; i++) {
            int ai = (base + i < NAT) ? base + i : NAT - 1;
            const float4* mrow = reinterpret_cast<const float4*>(g_msg + (size_t)ai * MSGS);
            if (lane < 26) reinterpret_cast<float4*>(ms + i * 104)[lane] = __ldg(mrow + lane);
        }
        __syncwarp();

        ull a1[4][4];
#pragma unroll
        for (int i = 0; i < 4; i++)
#pragma unroll
            for (int c = 0; c < 4; c++) a1[i][c] = pack2(b1c[c], 0.f);
        for (int k2 = 0; k2 < 49; k2++) {
            const ull* wr = wt1u + k2 * 128;
            ull w0 = wr[lane], w1 = wr[32+lane], w2 = wr[64+lane], w3 = wr[96+lane];
#pragma unroll
            for (int i = 0; i < 4; i++) {
                ull x2 = *reinterpret_cast<const ull*>(ms + i * 104 + 2 * k2);
                a1[i][0] = fma2(w0, x2, a1[i][0]);
                a1[i][1] = fma2(w1, x2, a1[i][1]);
                a1[i][2] = fma2(w2, x2, a1[i][2]);
                a1[i][3] = fma2(w3, x2, a1[i][3]);
            }
        }
        __syncwarp();
#pragma unroll
        for (int i = 0; i < 4; i++)
#pragma unroll
            for (int c = 0; c < 4; c++) {
                float lo, hi; unpack2(a1[i][c], lo, hi);
                hs[i * 128 + c * 32 + lane] = gelu_exact(lo + hi);
            }
        __syncwarp();

        ull a2[4][4];
#pragma unroll
        for (int i = 0; i < 4; i++)
#pragma unroll
            for (int c = 0; c < 4; c++) a2[i][c] = pack2(b2c[c], 0.f);
        for (int k2 = 0; k2 < 64; k2++) {
            const ull* wr = wt2u + k2 * 128;
            ull w0 = wr[lane], w1 = wr[32+lane], w2 = wr[64+lane], w3 = wr[96+lane];
#pragma unroll
            for (int i = 0; i < 4; i++) {
                ull x2 = *reinterpret_cast<const ull*>(hs + i * 128 + 2 * k2);
                a2[i][0] = fma2(w0, x2, a2[i][0]);
                a2[i][1] = fma2(w1, x2, a2[i][1]);
                a2[i][2] = fma2(w2, x2, a2[i][2]);
                a2[i][3] = fma2(w3, x2, a2[i][3]);
            }
        }
        __syncwarp();
        float h2v[4][4];
#pragma unroll
        for (int i = 0; i < 4; i++)
#pragma unroll
            for (int c = 0; c < 4; c++) {
                float lo, hi; unpack2(a2[i][c], lo, hi);
                h2v[i][c] = gelu_exact(lo + hi);
            }
#pragma unroll
        for (int i = 0; i < 4; i++)
#pragma unroll
            for (int c = 0; c < 4; c++) hs[i * 128 + c * 32 + lane] = h2v[i][c];
        __syncwarp();

        ull c0[4], c1[4], cc2[4];
#pragma unroll
        for (int i = 0; i < 4; i++) {
            c0[i] = pack2(bc0, 0.f); c1[i] = pack2(bc1, 0.f); cc2[i] = pack2(bc2, 0.f);
        }
        for (int k2 = 0; k2 < 64; k2++) {
            const ull* wr = wt3u + k2 * 68;
            ull w0 = wr[lane], w1 = wr[32 + lane], w2 = wr[c2i];
#pragma unroll
            for (int i = 0; i < 4; i++) {
                ull x2 = *reinterpret_cast<const ull*>(hs + i * 128 + 2 * k2);
                c0[i]  = fma2(w0, x2, c0[i]);
                c1[i]  = fma2(w1, x2, c1[i]);
                cc2[i] = fma2(w2, x2, cc2[i]);
            }
        }

#pragma unroll
        for (int i = 0; i < 4; i++) {
            int a = base + i;
            if (a >= NAT) break;
            float l0, h0, l1, h1, l2, h2;
            unpack2(c0[i], l0, h0); unpack2(c1[i], l1, h1); unpack2(cc2[i], l2, h2);
            float r0 = l0 + h0, r1 = l1 + h1, r2 = l2 + h2;
            if (lane == 0)      dq[a] = r0;
            else if (lane == 1) fo[a] = r0;
            else                da[(size_t)a * 64 + (lane - 2)] = r0;
            da[(size_t)a * 64 + (30 + lane)] = r1;
            if (lane < 2) da[(size_t)a * 64 + (62 + lane)] = r2;
        }
    }
}

extern "C" void kernel_launch(void* const* d_in, const int* in_sizes, int n_in,
                              void* d_out, int out_size) {
    const float *emb = 0, *pc = 0, *gs = 0, *gv = 0, *agh = 0;
    const float *W1 = 0, *b1 = 0, *W2 = 0, *b2 = 0, *W3 = 0, *b3 = 0;
    const int* pidx = 0;
    for (int i = 0; i < n_in; i++) {
        switch (in_sizes[i]) {
            case 3200000:  emb = (const float*)d_in[i]; break;
            case 50000:    pc  = (const float*)d_in[i]; break;
            case 16000000: gs  = (const float*)d_in[i]; break;
            case 48000000: gv  = (const float*)d_in[i]; break;
            case 32768:    agh = (const float*)d_in[i]; break;
            case 16512:    W1  = (const float*)d_in[i]; break;
            case 16384:    W2  = (const float*)d_in[i]; break;
            case 8448:     W3  = (const float*)d_in[i]; break;
            case 128:      if (!b1) b1 = (const float*)d_in[i];
                           else     b2 = (const float*)d_in[i]; break;
            case 66:       b3  = (const float*)d_in[i]; break;
            case 2000000:  pidx = (const int*)d_in[i]; break;
            default: break;
        }
    }
    float* out = (float*)d_out;
    (void)out_size;

    cudaFuncSetAttribute(k_atom, cudaFuncAttributeMaxDynamicSharedMemorySize, 131072);
    cudaFuncSetAttribute(k_mlp,  cudaFuncAttributeMaxDynamicSharedMemorySize, SMEM_MLP);

    const int* idxj = pidx + NP;   // pair_indices[1]

    k_hist<<<(NP + 255) / 256, 256>>>(gs, idxj);               // idx0
    k_scan<<<NBLK, SCB>>>();                                   // idx1
    k_place<<<(NP + 255) / 256, 256>>>(idxj);                  // idx2
    k_gatherw<<<(NAT + 7) / 8, 256>>>(gv);                     // idx3 <- profiled
    k_atom<<<NSM, 512, 131072>>>(emb, pc, agh);
    k_mlp<<<NSM, 512, SMEM_MLP>>>(W1, b1, W2, b2, W3, b3, out);
}

// round 16
// speedup vs baseline: 1.0391x; 1.0050x over previous
#include <cuda_runtime.h>
#include <math.h>
#include <stdint.h>

#define NAT   50000
#define NP    1000000
#define MSGS  104
#define NSM   152
#define SCB   512
#define NBLK  ((NAT + SCB - 1) / SCB)   /* 98 */
typedef unsigned long long ull;

__device__ float g_Msum2[(size_t)NAT * 144];
__device__ float g_S[NAT];                    // zero at load; k_atom re-zeroes
__device__ float g_msg[(size_t)NAT * MSGS];
__device__ int   g_cnt[NAT];                  // zero at load; gatherw re-zeroes
__device__ int   g_loff[NAT];
__device__ int   g_lcur[NAT];
__device__ int   g_bsum[NBLK];
__device__ int   g_bbase[NBLK];
__device__ int   g_plist[NP];
__device__ int   g_scan_done;                 // zero at load; scan re-zeroes

__device__ __forceinline__ ull pack2(float x, float y) {
    ull r; asm("mov.b64 %0, {%1, %2};" : "=l"(r) : "f"(x), "f"(y)); return r;
}
__device__ __forceinline__ ull dup2(float x) {
    ull r; asm("mov.b64 %0, {%1, %1};" : "=l"(r) : "f"(x)); return r;
}
__device__ __forceinline__ void unpack2(ull v, float& x, float& y) {
    asm("mov.b64 {%0, %1}, %2;" : "=f"(x), "=f"(y) : "l"(v));
}
__device__ __forceinline__ ull fma2(ull a, ull b, ull c) {
    ull d; asm("fma.rn.f32x2 %0, %1, %2, %3;" : "=l"(d) : "l"(a), "l"(b), "l"(c));
    return d;
}
__device__ __forceinline__ float gelu_exact(float x) {
    return 0.5f * x * (1.0f + erff(x * 0.70710678118654752440f));
}

// ---- k_hist: per-atom pair count + S ----
__global__ void __launch_bounds__(256) k_hist(const float* __restrict__ gs,
                                              const int* __restrict__ idxj) {
    int p = blockIdx.x * 256 + threadIdx.x;
    if (p >= NP) return;
    const float4* gs4 = reinterpret_cast<const float4*>(gs) + (size_t)p * 4;
    float s = 0.f;
#pragma unroll
    for (int k = 0; k < 4; k++) {
        float4 t = __ldg(gs4 + k);
        s += (t.x + t.y) + (t.z + t.w);
    }
    int a = __ldg(idxj + p);
    if (a < 0 || a >= NAT) return;
    atomicAdd(&g_cnt[a], 1);
    atomicAdd(&g_S[a], s);
}

// ---- k_scan: fused block-local + last-block global prefix ----
__global__ void __launch_bounds__(SCB) k_scan() {
    __shared__ int s[SCB];
    __shared__ int amLast;
    int b = blockIdx.x, t = threadIdx.x;
    int a = b * SCB + t;
    int c = (a < NAT) ? g_cnt[a] : 0;
    s[t] = c;
    __syncthreads();
    for (int off = 1; off < SCB; off <<= 1) {
        int v = (t >= off) ? s[t - off] : 0;
        __syncthreads();
        s[t] += v;
        __syncthreads();
    }
    int excl = s[t] - c;
    if (a < NAT) { g_loff[a] = excl; g_lcur[a] = excl; }
    if (t == SCB - 1) g_bsum[b] = s[SCB - 1];
    __threadfence();
    if (t == 0) amLast = (atomicAdd(&g_scan_done, 1) == NBLK - 1);
    __syncthreads();
    if (amLast) {
        int v = (t < NBLK) ? g_bsum[t] : 0;
        s[t] = v;
        __syncthreads();
        for (int off = 1; off < 128; off <<= 1) {
            int u = (t >= off && t < 128) ? s[t - off] : 0;
            __syncthreads();
            if (t < 128) s[t] += u;
            __syncthreads();
        }
        if (t < NBLK) g_bbase[t] = s[t] - v;
        if (t == 0) g_scan_done = 0;
    }
}

// ---- k_place ----
__global__ void __launch_bounds__(256) k_place(const int* __restrict__ idxj) {
    int p = blockIdx.x * 256 + threadIdx.x;
    if (p >= NP) return;
    int a = __ldg(idxj + p);
    if (a < 0 || a >= NAT) return;
    int pos = g_bbase[a >> 9] + atomicAdd(&g_lcur[a], 1);
    g_plist[pos] = p;
}

// ---- k_gatherw v3 (R15-exact) ----
__global__ void __launch_bounds__(256) k_gatherw(const float* __restrict__ gv) {
    int w = threadIdx.x >> 5, lane = threadIdx.x & 31;
    int a = blockIdx.x * 8 + w;
    if (a >= NAT) return;
    int g = lane & 15, half = lane >> 4;

    int beg = g_bbase[a >> 9] + g_loff[a];
    int cnt = g_cnt[a];

    float acc[9];
#pragma unroll
    for (int o = 0; o < 9; o++) acc[o] = 0.f;

    int p0 = (half < cnt) ? g_plist[beg + half] : -1;
    int p1 = (2 + half < cnt) ? g_plist[beg + 2 + half] : -1;
    float cx = 0.f, cy = 0.f, cz = 0.f;
    if (p0 >= 0) {
        const float* vp = gv + (size_t)p0 * 48;
        cx = __ldg(vp + g); cy = __ldg(vp + 16 + g); cz = __ldg(vp + 32 + g);
    }

    int rounds = (cnt + 1) >> 1;
    for (int r = 0; r < rounds; r++) {
        int i2 = 2 * (r + 2) + half;
        int p2 = (i2 < cnt) ? g_plist[beg + i2] : -1;
        float nx = 0.f, ny = 0.f, nz = 0.f;
        if (p1 >= 0) {
            const float* vp = gv + (size_t)p1 * 48;
            nx = __ldg(vp + g); ny = __ldg(vp + 16 + g); nz = __ldg(vp + 32 + g);
        }
#pragma unroll
        for (int o = 0; o < 9; o++) {
            int src = (g + o) & 15;
            float px = __shfl_sync(0xffffffffu, cx, src, 16);
            float py = __shfl_sync(0xffffffffu, cy, src, 16);
            float pz = __shfl_sync(0xffffffffu, cz, src, 16);
            acc[o] += cx * px + cy * py + cz * pz;
        }
        cx = nx; cy = ny; cz = nz;
        p1 = p2;
    }

#pragma unroll
    for (int o = 0; o < 9; o++)
        acc[o] += __shfl_xor_sync(0xffffffffu, acc[o], 16);

    if (half == 0) {
        float* dst = g_Msum2 + (size_t)a * 144;
#pragma unroll
        for (int o = 0; o < 9; o++) dst[o * 16 + g] = acc[o];
    }
    if (lane == 0) g_cnt[a] = 0;
}

// ---- k_atom (R15-exact) ----
__global__ void __launch_bounds__(512) k_atom(const float* __restrict__ emb,
                                              const float* __restrict__ pc,
                                              const float* __restrict__ agh) {
    extern __shared__ float aghs[];
    int tid = threadIdx.x;
    for (int i = tid; i < 32768; i += 512) {
        int f = i >> 9, rem = i & 511, g = rem >> 5, h = rem & 31;
        aghs[f * 512 + (g >> 1) * 64 + h * 2 + (g & 1)] = __ldg(agh + i);
    }
    __syncthreads();

    int lane = tid & 31, wid = tid >> 5;
    int gw = blockIdx.x * 16 + wid, GW = gridDim.x * 16;

    for (int base = gw * 4; base < NAT; base += GW * 4) {
        float e0[4], e1[4];
#pragma unroll
        for (int i = 0; i < 4; i++) {
            int ai = (base + i < NAT) ? base + i : NAT - 1;
            e0[i] = __ldg(emb + (size_t)ai * 64 + lane);
            e1[i] = __ldg(emb + (size_t)ai * 64 + 32 + lane);
        }
        ull T2[4][8];
#pragma unroll
        for (int i = 0; i < 4; i++)
#pragma unroll
            for (int g2 = 0; g2 < 8; g2++) T2[i][g2] = 0ull;

#pragma unroll 4
        for (int fl = 0; fl < 32; fl++) {
            ull x0 = dup2(__shfl_sync(0xffffffffu, e0[0], fl));
            ull x1 = dup2(__shfl_sync(0xffffffffu, e0[1], fl));
            ull x2 = dup2(__shfl_sync(0xffffffffu, e0[2], fl));
            ull x3 = dup2(__shfl_sync(0xffffffffu, e0[3], fl));
            const ull* ap = reinterpret_cast<const ull*>(aghs + fl * 512) + lane;
#pragma unroll
            for (int g2 = 0; g2 < 8; g2++) {
                ull av = ap[g2 * 32];
                T2[0][g2] = fma2(x0, av, T2[0][g2]);
                T2[1][g2] = fma2(x1, av, T2[1][g2]);
                T2[2][g2] = fma2(x2, av, T2[2][g2]);
                T2[3][g2] = fma2(x3, av, T2[3][g2]);
            }
        }
#pragma unroll 4
        for (int fl = 0; fl < 32; fl++) {
            ull x0 = dup2(__shfl_sync(0xffffffffu, e1[0], fl));
            ull x1 = dup2(__shfl_sync(0xffffffffu, e1[1], fl));
            ull x2 = dup2(__shfl_sync(0xffffffffu, e1[2], fl));
            ull x3 = dup2(__shfl_sync(0xffffffffu, e1[3], fl));
            const ull* ap = reinterpret_cast<const ull*>(aghs + (32 + fl) * 512) + lane;
#pragma unroll
            for (int g2 = 0; g2 < 8; g2++) {
                ull av = ap[g2 * 32];
                T2[0][g2] = fma2(x0, av, T2[0][g2]);
                T2[1][g2] = fma2(x1, av, T2[1][g2]);
                T2[2][g2] = fma2(x2, av, T2[2][g2]);
                T2[3][g2] = fma2(x3, av, T2[3][g2]);
            }
        }

#pragma unroll
        for (int i = 0; i < 4; i++) {
            int a = base + i;
            if (a >= NAT) break;
            float T[16];
#pragma unroll
            for (int g2 = 0; g2 < 8; g2++) unpack2(T2[i][g2], T[2*g2], T[2*g2+1]);

            const float* mr = g_Msum2 + (size_t)a * 144;
            float mv0 = mr[lane], mv1 = mr[32+lane], mv2 = mr[64+lane], mv3 = mr[96+lane];
            float mv4 = (lane < 16) ? mr[128 + lane] : 0.f;
            float Sv = g_S[a];
            float qv = __ldg(pc + a);

            float qd = 0.f, qo = 0.f, q8 = 0.f;
#pragma unroll
            for (int o = 0; o < 9; o++)
#pragma unroll
                for (int g = 0; g < 16; g++) {
                    const int idx = o * 16 + g;
                    float msrc = (idx < 32) ? mv0 : (idx < 64) ? mv1 : (idx < 96) ? mv2
                               : (idx < 128) ? mv3 : mv4;
                    float mm = __shfl_sync(0xffffffffu, msrc, idx & 31);
                    float t = T[g] * T[(g + o) & 15];
                    if (o == 0)      qd = fmaf(mm, t, qd);
                    else if (o == 8) q8 = fmaf(mm, t, q8);
                    else             qo = fmaf(mm, t, qo);
                }
            float Q = (qd + q8) + 2.f * qo;

            float* mg = g_msg + (size_t)a * MSGS;
            mg[lane]      = e0[i] * Sv;
            mg[32 + lane] = e1[i] * Sv;
            mg[64 + lane] = Q;
            if (lane < 8) mg[96 + lane] = (lane == 0) ? qv * Sv : 0.f;
            if (lane == 0) g_S[a] = 0.f;
        }
    }
}

// ---- k_mlp v5: 512 thr, 16 warps, 8 atoms/warp, k2-paired weights,
//      unified per-atom activation slot (msg/h1/h2 share 128 floats) ----
#define oWT1 0              /* 49 k2 x 128 x 2 = 12544 floats */
#define oWT2 12544          /* 64 k2 x 128 x 2 = 16384        */
#define oWT3 28928          /* 64 k2 x 68 x 2  =  8704        */
#define oB1  37632
#define oB2  37760
#define oB3  37888          /* 72 */
#define oXS  37960          /* 16 warps x 8 atoms x 128       */
#define SMEM_MLP ((37960 + 16384) * 4)

__global__ void __launch_bounds__(512) k_mlp(const float* __restrict__ W1,
                                             const float* __restrict__ b1,
                                             const float* __restrict__ W2,
                                             const float* __restrict__ b2,
                                             const float* __restrict__ W3,
                                             const float* __restrict__ b3,
                                             float* __restrict__ out) {
    extern __shared__ float sm[];
    int tid = threadIdx.x;
    for (int idx = tid; idx < 6272; idx += 512) {
        int k2 = idx >> 7, c = idx & 127;
        sm[oWT1 + idx*2]   = (2*k2   < 97) ? W1[(2*k2)  *128 + c] : 0.f;
        sm[oWT1 + idx*2+1] = (2*k2+1 < 97) ? W1[(2*k2+1)*128 + c] : 0.f;
    }
    for (int idx = tid; idx < 8192; idx += 512) {
        int k2 = idx >> 7, c = idx & 127;
        sm[oWT2 + idx*2]   = W2[(2*k2)  *128 + c];
        sm[oWT2 + idx*2+1] = W2[(2*k2+1)*128 + c];
    }
    for (int idx = tid; idx < 4352; idx += 512) {
        int k2 = idx / 68, c = idx - k2 * 68;
        sm[oWT3 + idx*2]   = (c < 66) ? W3[(2*k2)  *66 + c] : 0.f;
        sm[oWT3 + idx*2+1] = (c < 66) ? W3[(2*k2+1)*66 + c] : 0.f;
    }
    if (tid < 128) { sm[oB1 + tid] = b1[tid]; sm[oB2 + tid] = b2[tid]; }
    if (tid < 72)  sm[oB3 + tid] = (tid < 66) ? b3[tid] : 0.f;
    __syncthreads();

    int lane = tid & 31, w = tid >> 5;
    float* xs = sm + oXS + w * 1024;    // 8 atoms x 128 floats (msg/h1/h2 union)
    const ull* wt1u = reinterpret_cast<const ull*>(sm + oWT1);
    const ull* wt2u = reinterpret_cast<const ull*>(sm + oWT2);
    const ull* wt3u = reinterpret_cast<const ull*>(sm + oWT3);
    float b1c[4] = { sm[oB1+lane], sm[oB1+32+lane], sm[oB1+64+lane], sm[oB1+96+lane] };
    float b2c[4] = { sm[oB2+lane], sm[oB2+32+lane], sm[oB2+64+lane], sm[oB2+96+lane] };
    float bc0 = sm[oB3 + lane], bc1 = sm[oB3 + 32 + lane];
    float bc2 = sm[oB3 + 64 + (lane & 1)];
    int c2i = 64 + (lane & 1);

    float* da = out;
    float* dq = out + (size_t)NAT * 64;
    float* fo = out + (size_t)NAT * 65;

    int gw = blockIdx.x * 16 + w, GW = gridDim.x * 16;
    for (int base = gw * 8; base < NAT; base += GW * 8) {
        __syncwarp();   // prior-iteration layer-3 reads complete before restage
#pragma unroll
        for (int i = 0; i < 8; i++) {
            int ai = base + i; if (ai >= NAT) ai = NAT - 1;
            const float4* mrow = reinterpret_cast<const float4*>(g_msg + (size_t)ai * MSGS);
            if (lane < 26) reinterpret_cast<float4*>(xs + i * 128)[lane] = __ldg(mrow + lane);
        }
        __syncwarp();

        // ---- layer 1: 49 k2 (rows 0..97, row 97 zero-weighted) ----
        {
            ull a1[8][4];
#pragma unroll
            for (int i = 0; i < 8; i++)
#pragma unroll
                for (int c = 0; c < 4; c++) a1[i][c] = pack2(b1c[c], 0.f);
            for (int k2 = 0; k2 < 49; k2++) {
                const ull* wr = wt1u + k2 * 128;
                ull w0 = wr[lane], w1 = wr[32+lane], w2 = wr[64+lane], w3 = wr[96+lane];
#pragma unroll
                for (int i = 0; i < 8; i++) {
                    ull x2 = *reinterpret_cast<const ull*>(xs + i * 128 + 2 * k2);
                    a1[i][0] = fma2(w0, x2, a1[i][0]);
                    a1[i][1] = fma2(w1, x2, a1[i][1]);
                    a1[i][2] = fma2(w2, x2, a1[i][2]);
                    a1[i][3] = fma2(w3, x2, a1[i][3]);
                }
            }
            __syncwarp();
#pragma unroll
            for (int i = 0; i < 8; i++)
#pragma unroll
                for (int c = 0; c < 4; c++) {
                    float lo, hi; unpack2(a1[i][c], lo, hi);
                    xs[i * 128 + c * 32 + lane] = gelu_exact(lo + hi);
                }
            __syncwarp();
        }

        // ---- layer 2: 64 k2 ----
        {
            ull a2[8][4];
#pragma unroll
            for (int i = 0; i < 8; i++)
#pragma unroll
                for (int c = 0; c < 4; c++) a2[i][c] = pack2(b2c[c], 0.f);
            for (int k2 = 0; k2 < 64; k2++) {
                const ull* wr = wt2u + k2 * 128;
                ull w0 = wr[lane], w1 = wr[32+lane], w2 = wr[64+lane], w3 = wr[96+lane];
#pragma unroll
                for (int i = 0; i < 8; i++) {
                    ull x2 = *reinterpret_cast<const ull*>(xs + i * 128 + 2 * k2);
                    a2[i][0] = fma2(w0, x2, a2[i][0]);
                    a2[i][1] = fma2(w1, x2, a2[i][1]);
                    a2[i][2] = fma2(w2, x2, a2[i][2]);
                    a2[i][3] = fma2(w3, x2, a2[i][3]);
                }
            }
            __syncwarp();
#pragma unroll
            for (int i = 0; i < 8; i++)
#pragma unroll
                for (int c = 0; c < 4; c++) {
                    float lo, hi; unpack2(a2[i][c], lo, hi);
                    xs[i * 128 + c * 32 + lane] = gelu_exact(lo + hi);
                }
            __syncwarp();
        }

        // ---- layer 3: 64 k2, cols {lane, 32+lane, 64+(lane&1)} ----
        ull c0[8], c1[8], cc2[8];
#pragma unroll
        for (int i = 0; i < 8; i++) {
            c0[i] = pack2(bc0, 0.f); c1[i] = pack2(bc1, 0.f); cc2[i] = pack2(bc2, 0.f);
        }
        for (int k2 = 0; k2 < 64; k2++) {
            const ull* wr = wt3u + k2 * 68;
            ull w0 = wr[lane], w1 = wr[32 + lane], w2 = wr[c2i];
#pragma unroll
            for (int i = 0; i < 8; i++) {
                ull x2 = *reinterpret_cast<const ull*>(xs + i * 128 + 2 * k2);
                c0[i]  = fma2(w0, x2, c0[i]);
                c1[i]  = fma2(w1, x2, c1[i]);
                cc2[i] = fma2(w2, x2, cc2[i]);
            }
        }

#pragma unroll
        for (int i = 0; i < 8; i++) {
            int a = base + i;
            if (a >= NAT) break;
            float l0, h0, l1, h1, l2, h2;
            unpack2(c0[i], l0, h0); unpack2(c1[i], l1, h1); unpack2(cc2[i], l2, h2);
            float r0 = l0 + h0, r1 = l1 + h1, r2 = l2 + h2;
            if (lane == 0)      dq[a] = r0;
            else if (lane == 1) fo[a] = r0;
            else                da[(size_t)a * 64 + (lane - 2)] = r0;
            da[(size_t)a * 64 + (30 + lane)] = r1;
            if (lane < 2) da[(size_t)a * 64 + (62 + lane)] = r2;
        }
    }
}

extern "C" void kernel_launch(void* const* d_in, const int* in_sizes, int n_in,
                              void* d_out, int out_size) {
    const float *emb = 0, *pc = 0, *gs = 0, *gv = 0, *agh = 0;
    const float *W1 = 0, *b1 = 0, *W2 = 0, *b2 = 0, *W3 = 0, *b3 = 0;
    const int* pidx = 0;
    for (int i = 0; i < n_in; i++) {
        switch (in_sizes[i]) {
            case 3200000:  emb = (const float*)d_in[i]; break;
            case 50000:    pc  = (const float*)d_in[i]; break;
            case 16000000: gs  = (const float*)d_in[i]; break;
            case 48000000: gv  = (const float*)d_in[i]; break;
            case 32768:    agh = (const float*)d_in[i]; break;
            case 16512:    W1  = (const float*)d_in[i]; break;
            case 16384:    W2  = (const float*)d_in[i]; break;
            case 8448:     W3  = (const float*)d_in[i]; break;
            case 128:      if (!b1) b1 = (const float*)d_in[i];
                           else     b2 = (const float*)d_in[i]; break;
            case 66:       b3  = (const float*)d_in[i]; break;
            case 2000000:  pidx = (const int*)d_in[i]; break;
            default: break;
        }
    }
    float* out = (float*)d_out;
    (void)out_size;

    cudaFuncSetAttribute(k_atom, cudaFuncAttributeMaxDynamicSharedMemorySize, 131072);
    cudaFuncSetAttribute(k_mlp,  cudaFuncAttributeMaxDynamicSharedMemorySize, SMEM_MLP);

    const int* idxj = pidx + NP;   // pair_indices[1]

    k_hist<<<(NP + 255) / 256, 256>>>(gs, idxj);               // idx0
    k_scan<<<NBLK, SCB>>>();                                   // idx1
    k_place<<<(NP + 255) / 256, 256>>>(idxj);                  // idx2
    k_gatherw<<<(NAT + 7) / 8, 256>>>(gv);                     // idx3 <- profiled
    k_atom<<<NSM, 512, 131072>>>(emb, pc, agh);
    k_mlp<<<NSM, 512, SMEM_MLP>>>(W1, b1, W2, b2, W3, b3, out);
}

// round 17
// speedup vs baseline: 1.0640x; 1.0239x over previous
#include <cuda_runtime.h>
#include <math.h>
#include <stdint.h>

#define NAT   50000
#define NP    1000000
#define MSGS  104
#define NSM   152
#define SCB   512
#define NBLK  ((NAT + SCB - 1) / SCB)   /* 98 */
typedef unsigned long long ull;

__device__ float g_Msum2[(size_t)NAT * 144];
__device__ float g_S[NAT];                    // zero at load; k_atom re-zeroes
__device__ float g_msg[(size_t)NAT * MSGS];
__device__ int   g_cnt[NAT];                  // zero at load; gatherw re-zeroes
__device__ int   g_loff[NAT];
__device__ int   g_lcur[NAT];
__device__ int   g_bsum[NBLK];
__device__ int   g_bbase[NBLK];
__device__ int   g_plist[NP];
__device__ int   g_scan_done;                 // zero at load; scan re-zeroes

__device__ __forceinline__ ull pack2(float x, float y) {
    ull r; asm("mov.b64 %0, {%1, %2};" : "=l"(r) : "f"(x), "f"(y)); return r;
}
__device__ __forceinline__ void unpack2(ull v, float& x, float& y) {
    asm("mov.b64 {%0, %1}, %2;" : "=f"(x), "=f"(y) : "l"(v));
}
__device__ __forceinline__ ull fma2(ull a, ull b, ull c) {
    ull d; asm("fma.rn.f32x2 %0, %1, %2, %3;" : "=l"(d) : "l"(a), "l"(b), "l"(c));
    return d;
}
__device__ __forceinline__ float gelu_exact(float x) {
    return 0.5f * x * (1.0f + erff(x * 0.70710678118654752440f));
}

// ---- k_hist ----
__global__ void __launch_bounds__(256) k_hist(const float* __restrict__ gs,
                                              const int* __restrict__ idxj) {
    int p = blockIdx.x * 256 + threadIdx.x;
    if (p >= NP) return;
    const float4* gs4 = reinterpret_cast<const float4*>(gs) + (size_t)p * 4;
    float s = 0.f;
#pragma unroll
    for (int k = 0; k < 4; k++) {
        float4 t = __ldg(gs4 + k);
        s += (t.x + t.y) + (t.z + t.w);
    }
    int a = __ldg(idxj + p);
    if (a < 0 || a >= NAT) return;
    atomicAdd(&g_cnt[a], 1);
    atomicAdd(&g_S[a], s);
}

// ---- k_scan (R15-exact) ----
__global__ void __launch_bounds__(SCB) k_scan() {
    __shared__ int s[SCB];
    __shared__ int amLast;
    int b = blockIdx.x, t = threadIdx.x;
    int a = b * SCB + t;
    int c = (a < NAT) ? g_cnt[a] : 0;
    s[t] = c;
    __syncthreads();
    for (int off = 1; off < SCB; off <<= 1) {
        int v = (t >= off) ? s[t - off] : 0;
        __syncthreads();
        s[t] += v;
        __syncthreads();
    }
    int excl = s[t] - c;
    if (a < NAT) { g_loff[a] = excl; g_lcur[a] = excl; }
    if (t == SCB - 1) g_bsum[b] = s[SCB - 1];
    __threadfence();
    if (t == 0) amLast = (atomicAdd(&g_scan_done, 1) == NBLK - 1);
    __syncthreads();
    if (amLast) {
        int v = (t < NBLK) ? g_bsum[t] : 0;
        s[t] = v;
        __syncthreads();
        for (int off = 1; off < 128; off <<= 1) {
            int u = (t >= off && t < 128) ? s[t - off] : 0;
            __syncthreads();
            if (t < 128) s[t] += u;
            __syncthreads();
        }
        if (t < NBLK) g_bbase[t] = s[t] - v;
        if (t == 0) g_scan_done = 0;
    }
}

// ---- k_place ----
__global__ void __launch_bounds__(256) k_place(const int* __restrict__ idxj) {
    int p = blockIdx.x * 256 + threadIdx.x;
    if (p >= NP) return;
    int a = __ldg(idxj + p);
    if (a < 0 || a >= NAT) return;
    int pos = g_bbase[a >> 9] + atomicAdd(&g_lcur[a], 1);
    g_plist[pos] = p;
}

// ---- k_gatherw v4: 2-round gv pipeline, 3-round plist prefetch ----
__global__ void __launch_bounds__(256) k_gatherw(const float* __restrict__ gv) {
    int w = threadIdx.x >> 5, lane = threadIdx.x & 31;
    int a = blockIdx.x * 8 + w;
    if (a >= NAT) return;
    int g = lane & 15, half = lane >> 4;

    int beg = g_bbase[a >> 9] + g_loff[a];
    int cnt = g_cnt[a];

    float acc[9];
#pragma unroll
    for (int o = 0; o < 9; o++) acc[o] = 0.f;

    // indices for rounds 0,1,2; data for rounds 0,1
    int p0 = (half < cnt)     ? g_plist[beg + half]     : -1;
    int p1 = (2 + half < cnt) ? g_plist[beg + 2 + half] : -1;
    int p2 = (4 + half < cnt) ? g_plist[beg + 4 + half] : -1;
    float ax = 0.f, ay = 0.f, az = 0.f;
    float bx = 0.f, by = 0.f, bz = 0.f;
    if (p0 >= 0) {
        const float* vp = gv + (size_t)p0 * 48;
        ax = __ldg(vp + g); ay = __ldg(vp + 16 + g); az = __ldg(vp + 32 + g);
    }
    if (p1 >= 0) {
        const float* vp = gv + (size_t)p1 * 48;
        bx = __ldg(vp + g); by = __ldg(vp + 16 + g); bz = __ldg(vp + 32 + g);
    }

    int rounds = (cnt + 1) >> 1;
    for (int r = 0; r < rounds; r++) {
        // index for round r+3, data for round r+2
        int i3 = 2 * (r + 3) + half;
        int p3 = (i3 < cnt) ? g_plist[beg + i3] : -1;
        float nx = 0.f, ny = 0.f, nz = 0.f;
        if (p2 >= 0) {
            const float* vp = gv + (size_t)p2 * 48;
            nx = __ldg(vp + g); ny = __ldg(vp + 16 + g); nz = __ldg(vp + 32 + g);
        }
#pragma unroll
        for (int o = 0; o < 9; o++) {
            int src = (g + o) & 15;
            float px = __shfl_sync(0xffffffffu, ax, src, 16);
            float py = __shfl_sync(0xffffffffu, ay, src, 16);
            float pz = __shfl_sync(0xffffffffu, az, src, 16);
            acc[o] += ax * px + ay * py + az * pz;
        }
        ax = bx; ay = by; az = bz;
        bx = nx; by = ny; bz = nz;
        p2 = p3;
    }

#pragma unroll
    for (int o = 0; o < 9; o++)
        acc[o] += __shfl_xor_sync(0xffffffffu, acc[o], 16);

    if (half == 0) {
        float* dst = g_Msum2 + (size_t)a * 144;
#pragma unroll
        for (int o = 0; o < 9; o++) dst[o * 16 + g] = acc[o];
    }
    if (lane == 0) g_cnt[a] = 0;
}

// ---- k_atom v2: e-values pre-duplicated in smem (kills shfl+pack per fl) ----
// smem: aghs (32768 f) + edup (16 warps x 256 ull = 8192 f). 160 KB total.
#define ATOM_SMEM ((32768 + 8192) * 4)
__global__ void __launch_bounds__(512) k_atom(const float* __restrict__ emb,
                                              const float* __restrict__ pc,
                                              const float* __restrict__ agh) {
    extern __shared__ float aghs[];
    ull* edup = reinterpret_cast<ull*>(aghs + 32768);
    int tid = threadIdx.x;
    for (int i = tid; i < 32768; i += 512) {
        int f = i >> 9, rem = i & 511, g = rem >> 5, h = rem & 31;
        aghs[f * 512 + (g >> 1) * 64 + h * 2 + (g & 1)] = __ldg(agh + i);
    }
    __syncthreads();

    int lane = tid & 31, wid = tid >> 5;
    ull* ed = edup + wid * 256;              // [f][atom] of dup-packed ull
    int gw = blockIdx.x * 16 + wid, GW = gridDim.x * 16;

    for (int base = gw * 4; base < NAT; base += GW * 4) {
        float e0[4], e1[4];
#pragma unroll
        for (int i = 0; i < 4; i++) {
            int ai = (base + i < NAT) ? base + i : NAT - 1;
            e0[i] = __ldg(emb + (size_t)ai * 64 + lane);
            e1[i] = __ldg(emb + (size_t)ai * 64 + 32 + lane);
        }
        __syncwarp();
#pragma unroll
        for (int i = 0; i < 4; i++) {
            ed[lane * 4 + i]        = pack2(e0[i], e0[i]);
            ed[(32 + lane) * 4 + i] = pack2(e1[i], e1[i]);
        }
        __syncwarp();

        ull T2[4][8];
#pragma unroll
        for (int i = 0; i < 4; i++)
#pragma unroll
            for (int g2 = 0; g2 < 8; g2++) T2[i][g2] = 0ull;

#pragma unroll 4
        for (int fl = 0; fl < 64; fl++) {
            ull x0 = ed[fl * 4 + 0];
            ull x1 = ed[fl * 4 + 1];
            ull x2 = ed[fl * 4 + 2];
            ull x3 = ed[fl * 4 + 3];
            const ull* ap = reinterpret_cast<const ull*>(aghs + fl * 512) + lane;
#pragma unroll
            for (int g2 = 0; g2 < 8; g2++) {
                ull av = ap[g2 * 32];
                T2[0][g2] = fma2(x0, av, T2[0][g2]);
                T2[1][g2] = fma2(x1, av, T2[1][g2]);
                T2[2][g2] = fma2(x2, av, T2[2][g2]);
                T2[3][g2] = fma2(x3, av, T2[3][g2]);
            }
        }

#pragma unroll
        for (int i = 0; i < 4; i++) {
            int a = base + i;
            if (a >= NAT) break;
            float T[16];
#pragma unroll
            for (int g2 = 0; g2 < 8; g2++) unpack2(T2[i][g2], T[2*g2], T[2*g2+1]);

            const float* mr = g_Msum2 + (size_t)a * 144;
            float mv0 = mr[lane], mv1 = mr[32+lane], mv2 = mr[64+lane], mv3 = mr[96+lane];
            float mv4 = (lane < 16) ? mr[128 + lane] : 0.f;
            float Sv = g_S[a];
            float qv = __ldg(pc + a);

            float qd = 0.f, qo = 0.f, q8 = 0.f;
#pragma unroll
            for (int o = 0; o < 9; o++)
#pragma unroll
                for (int g = 0; g < 16; g++) {
                    const int idx = o * 16 + g;
                    float msrc = (idx < 32) ? mv0 : (idx < 64) ? mv1 : (idx < 96) ? mv2
                               : (idx < 128) ? mv3 : mv4;
                    float mm = __shfl_sync(0xffffffffu, msrc, idx & 31);
                    float t = T[g] * T[(g + o) & 15];
                    if (o == 0)      qd = fmaf(mm, t, qd);
                    else if (o == 8) q8 = fmaf(mm, t, q8);
                    else             qo = fmaf(mm, t, qo);
                }
            float Q = (qd + q8) + 2.f * qo;

            float* mg = g_msg + (size_t)a * MSGS;
            mg[lane]      = e0[i] * Sv;
            mg[32 + lane] = e1[i] * Sv;
            mg[64 + lane] = Q;
            if (lane < 8) mg[96 + lane] = (lane == 0) ? qv * Sv : 0.f;
            if (lane == 0) g_S[a] = 0.f;
        }
    }
}

// ---- k_mlp v5 (R16-exact) ----
#define oWT1 0
#define oWT2 12544
#define oWT3 28928
#define oB1  37632
#define oB2  37760
#define oB3  37888
#define oXS  37960
#define SMEM_MLP ((37960 + 16384) * 4)

__global__ void __launch_bounds__(512) k_mlp(const float* __restrict__ W1,
                                             const float* __restrict__ b1,
                                             const float* __restrict__ W2,
                                             const float* __restrict__ b2,
                                             const float* __restrict__ W3,
                                             const float* __restrict__ b3,
                                             float* __restrict__ out) {
    extern __shared__ float sm[];
    int tid = threadIdx.x;
    for (int idx = tid; idx < 6272; idx += 512) {
        int k2 = idx >> 7, c = idx & 127;
        sm[oWT1 + idx*2]   = (2*k2   < 97) ? W1[(2*k2)  *128 + c] : 0.f;
        sm[oWT1 + idx*2+1] = (2*k2+1 < 97) ? W1[(2*k2+1)*128 + c] : 0.f;
    }
    for (int idx = tid; idx < 8192; idx += 512) {
        int k2 = idx >> 7, c = idx & 127;
        sm[oWT2 + idx*2]   = W2[(2*k2)  *128 + c];
        sm[oWT2 + idx*2+1] = W2[(2*k2+1)*128 + c];
    }
    for (int idx = tid; idx < 4352; idx += 512) {
        int k2 = idx / 68, c = idx - k2 * 68;
        sm[oWT3 + idx*2]   = (c < 66) ? W3[(2*k2)  *66 + c] : 0.f;
        sm[oWT3 + idx*2+1] = (c < 66) ? W3[(2*k2+1)*66 + c] : 0.f;
    }
    if (tid < 128) { sm[oB1 + tid] = b1[tid]; sm[oB2 + tid] = b2[tid]; }
    if (tid < 72)  sm[oB3 + tid] = (tid < 66) ? b3[tid] : 0.f;
    __syncthreads();

    int lane = tid & 31, w = tid >> 5;
    float* xs = sm + oXS + w * 1024;
    const ull* wt1u = reinterpret_cast<const ull*>(sm + oWT1);
    const ull* wt2u = reinterpret_cast<const ull*>(sm + oWT2);
    const ull* wt3u = reinterpret_cast<const ull*>(sm + oWT3);
    float b1c[4] = { sm[oB1+lane], sm[oB1+32+lane], sm[oB1+64+lane], sm[oB1+96+lane] };
    float b2c[4] = { sm[oB2+lane], sm[oB2+32+lane], sm[oB2+64+lane], sm[oB2+96+lane] };
    float bc0 = sm[oB3 + lane], bc1 = sm[oB3 + 32 + lane];
    float bc2 = sm[oB3 + 64 + (lane & 1)];
    int c2i = 64 + (lane & 1);

    float* da = out;
    float* dq = out + (size_t)NAT * 64;
    float* fo = out + (size_t)NAT * 65;

    int gw = blockIdx.x * 16 + w, GW = gridDim.x * 16;
    for (int base = gw * 8; base < NAT; base += GW * 8) {
        __syncwarp();
#pragma unroll
        for (int i = 0; i < 8; i++) {
            int ai = base + i; if (ai >= NAT) ai = NAT - 1;
            const float4* mrow = reinterpret_cast<const float4*>(g_msg + (size_t)ai * MSGS);
            if (lane < 26) reinterpret_cast<float4*>(xs + i * 128)[lane] = __ldg(mrow + lane);
        }
        __syncwarp();

        {
            ull a1[8][4];
#pragma unroll
            for (int i = 0; i < 8; i++)
#pragma unroll
                for (int c = 0; c < 4; c++) a1[i][c] = pack2(b1c[c], 0.f);
            for (int k2 = 0; k2 < 49; k2++) {
                const ull* wr = wt1u + k2 * 128;
                ull w0 = wr[lane], w1 = wr[32+lane], w2 = wr[64+lane], w3 = wr[96+lane];
#pragma unroll
                for (int i = 0; i < 8; i++) {
                    ull x2 = *reinterpret_cast<const ull*>(xs + i * 128 + 2 * k2);
                    a1[i][0] = fma2(w0, x2, a1[i][0]);
                    a1[i][1] = fma2(w1, x2, a1[i][1]);
                    a1[i][2] = fma2(w2, x2, a1[i][2]);
                    a1[i][3] = fma2(w3, x2, a1[i][3]);
                }
            }
            __syncwarp();
#pragma unroll
            for (int i = 0; i < 8; i++)
#pragma unroll
                for (int c = 0; c < 4; c++) {
                    float lo, hi; unpack2(a1[i][c], lo, hi);
                    xs[i * 128 + c * 32 + lane] = gelu_exact(lo + hi);
                }
            __syncwarp();
        }

        {
            ull a2[8][4];
#pragma unroll
            for (int i = 0; i < 8; i++)
#pragma unroll
                for (int c = 0; c < 4; c++) a2[i][c] = pack2(b2c[c], 0.f);
            for (int k2 = 0; k2 < 64; k2++) {
                const ull* wr = wt2u + k2 * 128;
                ull w0 = wr[lane], w1 = wr[32+lane], w2 = wr[64+lane], w3 = wr[96+lane];
#pragma unroll
                for (int i = 0; i < 8; i++) {
                    ull x2 = *reinterpret_cast<const ull*>(xs + i * 128 + 2 * k2);
                    a2[i][0] = fma2(w0, x2, a2[i][0]);
                    a2[i][1] = fma2(w1, x2, a2[i][1]);
                    a2[i][2] = fma2(w2, x2, a2[i][2]);
                    a2[i][3] = fma2(w3, x2, a2[i][3]);
                }
            }
            __syncwarp();
#pragma unroll
            for (int i = 0; i < 8; i++)
#pragma unroll
                for (int c = 0; c < 4; c++) {
                    float lo, hi; unpack2(a2[i][c], lo, hi);
                    xs[i * 128 + c * 32 + lane] = gelu_exact(lo + hi);
                }
            __syncwarp();
        }

        ull c0[8], c1[8], cc2[8];
#pragma unroll
        for (int i = 0; i < 8; i++) {
            c0[i] = pack2(bc0, 0.f); c1[i] = pack2(bc1, 0.f); cc2[i] = pack2(bc2, 0.f);
        }
        for (int k2 = 0; k2 < 64; k2++) {
            const ull* wr = wt3u + k2 * 68;
            ull w0 = wr[lane], w1 = wr[32 + lane], w2 = wr[c2i];
#pragma unroll
            for (int i = 0; i < 8; i++) {
                ull x2 = *reinterpret_cast<const ull*>(xs + i * 128 + 2 * k2);
                c0[i]  = fma2(w0, x2, c0[i]);
                c1[i]  = fma2(w1, x2, c1[i]);
                cc2[i] = fma2(w2, x2, cc2[i]);
            }
        }

#pragma unroll
        for (int i = 0; i < 8; i++) {
            int a = base + i;
            if (a >= NAT) break;
            float l0, h0, l1, h1, l2, h2;
            unpack2(c0[i], l0, h0); unpack2(c1[i], l1, h1); unpack2(cc2[i], l2, h2);
            float r0 = l0 + h0, r1 = l1 + h1, r2 = l2 + h2;
            if (lane == 0)      dq[a] = r0;
            else if (lane == 1) fo[a] = r0;
            else                da[(size_t)a * 64 + (lane - 2)] = r0;
            da[(size_t)a * 64 + (30 + lane)] = r1;
            if (lane < 2) da[(size_t)a * 64 + (62 + lane)] = r2;
        }
    }
}

extern "C" void kernel_launch(void* const* d_in, const int* in_sizes, int n_in,
                              void* d_out, int out_size) {
    const float *emb = 0, *pc = 0, *gs = 0, *gv = 0, *agh = 0;
    const float *W1 = 0, *b1 = 0, *W2 = 0, *b2 = 0, *W3 = 0, *b3 = 0;
    const int* pidx = 0;
    for (int i = 0; i < n_in; i++) {
        switch (in_sizes[i]) {
            case 3200000:  emb = (const float*)d_in[i]; break;
            case 50000:    pc  = (const float*)d_in[i]; break;
            case 16000000: gs  = (const float*)d_in[i]; break;
            case 48000000: gv  = (const float*)d_in[i]; break;
            case 32768:    agh = (const float*)d_in[i]; break;
            case 16512:    W1  = (const float*)d_in[i]; break;
            case 16384:    W2  = (const float*)d_in[i]; break;
            case 8448:     W3  = (const float*)d_in[i]; break;
            case 128:      if (!b1) b1 = (const float*)d_in[i];
                           else     b2 = (const float*)d_in[i]; break;
            case 66:       b3  = (const float*)d_in[i]; break;
            case 2000000:  pidx = (const int*)d_in[i]; break;
            default: break;
        }
    }
    float* out = (float*)d_out;
    (void)out_size;

    cudaFuncSetAttribute(k_atom, cudaFuncAttributeMaxDynamicSharedMemorySize, ATOM_SMEM);
    cudaFuncSetAttribute(k_mlp,  cudaFuncAttributeMaxDynamicSharedMemorySize, SMEM_MLP);

    const int* idxj = pidx + NP;   // pair_indices[1]

    k_hist<<<(NP + 255) / 256, 256>>>(gs, idxj);               // idx0
    k_scan<<<NBLK, SCB>>>();                                   // idx1
    k_place<<<(NP + 255) / 256, 256>>>(idxj);                  // idx2
    k_gatherw<<<(NAT + 7) / 8, 256>>>(gv);                     // idx3 <- profiled
    k_atom<<<NSM, 512, ATOM_SMEM>>>(emb, pc, agh);
    k_mlp<<<NSM, 512, SMEM_MLP>>>(W1, b1, W2, b2, W3, b3, out);
}